// round 15
// baseline (speedup 1.0000x reference)
#include <cuda_runtime.h>

#define T 64             // threads per block = rows per block
#define RPB 64
#define NCOLS 14
#define IN_F4 (RPB * NCOLS / 4)   // 224 float4 per block = 3.5 per thread
#define OUT_F4 (RPB * 3 / 4)      // 48 float4 per block

__global__ __launch_bounds__(T, 32)   // 32 CTAs/SM (2048 threads, CTA-slot max)
void indicator_kernel(const float4* __restrict__ in4, float4* __restrict__ out4) {
    __shared__ float s_in[RPB * NCOLS];   // 3584 B
    __shared__ float s_out[RPB * 3];      //  768 B

    const int tid = threadIdx.x;
    const int bid = blockIdx.x;
    float4* s4 = (float4*)s_in;
    const int base = bid * IN_F4;         // max 31249*224 = 7.0M — fits int32

    // ---- coalesced vectorized load: 64 rows -> smem ----
    // 224 float4 = 3 * 64 + 32 ; grid exact (2M % 64 == 0), no tails anywhere.
    #pragma unroll
    for (int i = 0; i < 3; i++)
        s4[tid + i * T] = in4[base + tid + i * T];
    if (tid < IN_F4 - 3 * T)              // first 32 threads take the remainder
        s4[tid + 3 * T] = in4[base + tid + 3 * T];
    __syncthreads();

    // ---- per-row compute: one row per thread ----
    {
        const float*  r  = &s_in[tid * NCOLS];
        const float2* r2 = (const float2*)r;          // 56*t bytes -> 8B aligned
        const float2 oc  = r2[0];   // cols 0,1
        const float  lw  = r[5];
        const float  uw  = r[6];
        const float2 ms  = r2[4];   // cols 8,9
        const float2 sbv = r2[5];   // cols 10,11
        const float2 mbl = r2[6];   // cols 12,13
        const float ha_open = oc.x, ha_close = oc.y;
        const float ma = ms.x, srsi = ms.y;
        const float ssig = sbv.x, bu = sbv.y;
        const float bm = mbl.x,  bl = mbl.y;

        const bool  bullish = ha_close > ha_open;
        const bool  bearish = ha_close < ha_open;
        const float body    = fabsf(ha_close - ha_open);
        const bool  sb = bullish && (body > 0.5f) && (uw < 1e-6f);  // strong_bullish
        const bool  sB = bearish && (body > 0.5f) && (lw < 1e-6f);  // strong_bearish

        const float ha2 = sb ? 0.8f : 0.0f;
        const float ha0 = sB ? 0.8f : 0.0f;

        const float width = (bu - bl) / bm;
        const float pp    = (ha_close - bl) / (bu - bl);
        // structurally false, kept for exact fidelity (NaN behavior identical):
        const bool  sqexp = (width < 0.1f) && (width > 0.2f);
        const float sqf   = sqexp ? 0.9f : 0.0f;

        const bool pp_lo = pp < 0.2f;
        const bool pp_hi = pp > 0.8f;
        const float bb2 = (pp_lo ? 0.8f : 0.0f) + sqf;
        const float bb0 = (pp_hi ? 0.8f : 0.0f) + sqf;

        const float st2 = (srsi < 0.2f) ? 0.8f : 0.0f;
        const float st0 = (srsi > 0.8f) ? 0.8f : 0.0f;

        const bool  ma_up = ma > 0.1f;
        const bool  ma_dn = ma < -0.1f;
        const float ma2 = ma_up ? 0.7f : 0.0f;
        const float ma0 = ma_dn ? 0.7f : 0.0f;

        const bool st_dn = ssig < -0.1f;
        const bool st_up = ssig > 0.1f;

        // OR of all 3-of-4 conjunctions == majority(>=3 of 4)
        const bool long_sig  = ((int)sb + (int)ma_up + (int)st_dn + (int)pp_lo) >= 3;
        const bool short_sig = ((int)sB + (int)ma_dn + (int)st_up + (int)pp_hi) >= 3;

        const float hms2 = long_sig  ? 0.9f : 0.0f;
        const float hms0 = short_sig ? 0.9f : 0.0f;

        const float col0 = ha0 + ma0 + st0 + bb0 + 2.0f * hms0;
        const float col2 = ha2 + ma2 + st2 + bb2 + 2.0f * hms2;
        const float col1 = 1.5f;

        const float m  = fmaxf(fmaxf(col0, col2), col1);
        const float e0 = __expf(col0 - m);
        const float e1 = __expf(col1 - m);
        const float e2 = __expf(col2 - m);
        const float inv = 1.0f / (e0 + e1 + e2);

        s_out[tid * 3 + 0] = e0 * inv;
        s_out[tid * 3 + 1] = e1 * inv;
        s_out[tid * 3 + 2] = e2 * inv;
    }
    __syncthreads();

    // ---- coalesced vectorized store ----
    const float4* so4 = (const float4*)s_out;
    const int obase = bid * OUT_F4;       // max 31249*48 = 1.5M
    if (tid < OUT_F4)                     // 48 of 64 threads
        out4[obase + tid] = so4[tid];
}

extern "C" void kernel_launch(void* const* d_in, const int* in_sizes, int n_in,
                              void* d_out, int out_size) {
    const float4* in4 = (const float4*)d_in[0];
    float4* out4 = (float4*)d_out;
    const int n = in_sizes[0] / NCOLS;       // 2,000,000 rows (divisible by 64)
    const int grid = n / RPB;                // 31250 blocks, all full
    indicator_kernel<<<grid, T>>>(in4, out4);
}

// round 16
// speedup vs baseline: 1.3179x; 1.3179x over previous
#include <cuda_runtime.h>

#define T 128            // threads per block = rows per block
#define RPB 128
#define NCOLS 14
#define IN_F4 (RPB * NCOLS / 4)   // 448 float4 per block
#define WF4 112                   // float4 per warp chunk (32 rows * 14 / 4)

__global__ __launch_bounds__(T, 16)   // 16 CTAs/SM (2048 threads)
void indicator_kernel(const float4* __restrict__ in4, float* __restrict__ out) {
    __shared__ float s_in[RPB * NCOLS];   // 7168 B
    __shared__ float s_out[RPB * 3];      // 1536 B

    const int tid = threadIdx.x;
    const int w   = tid >> 5;             // warp 0..3
    const int l   = tid & 31;             // lane
    const int bid = blockIdx.x;
    float4* s4 = (float4*)s_in;

    // ---- warp-local load: warp w loads float4 [w*112, (w+1)*112) of this tile ----
    // These 448 floats are exactly rows [w*32, (w+1)*32) — no cross-warp sharing.
    const int base = bid * IN_F4 + w * WF4;   // global float4 index (fits int32)
    const int sb   = w * WF4;                 // smem float4 index
    #pragma unroll
    for (int i = 0; i < 3; i++)
        s4[sb + l + i * 32] = in4[base + l + i * 32];
    if (l < WF4 - 96)                         // first 16 lanes take the remainder
        s4[sb + l + 96] = in4[base + l + 96];
    __syncwarp();                             // warp-only: no cross-warp coupling

    // ---- per-row compute: one row per thread (reads only own warp's chunk) ----
    {
        const float*  r  = &s_in[tid * NCOLS];
        const float2* r2 = (const float2*)r;          // 56*t bytes -> 8B aligned
        const float2 oc  = r2[0];   // cols 0,1
        const float  lw  = r[5];
        const float  uw  = r[6];
        const float2 ms  = r2[4];   // cols 8,9
        const float2 sbv = r2[5];   // cols 10,11
        const float2 mbl = r2[6];   // cols 12,13
        const float ha_open = oc.x, ha_close = oc.y;
        const float ma = ms.x, srsi = ms.y;
        const float ssig = sbv.x, bu = sbv.y;
        const float bm = mbl.x,  bl = mbl.y;

        const bool  bullish = ha_close > ha_open;
        const bool  bearish = ha_close < ha_open;
        const float body    = fabsf(ha_close - ha_open);
        const bool  sb_ = bullish && (body > 0.5f) && (uw < 1e-6f);  // strong_bullish
        const bool  sB_ = bearish && (body > 0.5f) && (lw < 1e-6f);  // strong_bearish

        const float ha2 = sb_ ? 0.8f : 0.0f;
        const float ha0 = sB_ ? 0.8f : 0.0f;

        const float width = (bu - bl) / bm;
        const float pp    = (ha_close - bl) / (bu - bl);
        // structurally false, kept for exact fidelity (NaN behavior identical):
        const bool  sqexp = (width < 0.1f) && (width > 0.2f);
        const float sqf   = sqexp ? 0.9f : 0.0f;

        const bool pp_lo = pp < 0.2f;
        const bool pp_hi = pp > 0.8f;
        const float bb2 = (pp_lo ? 0.8f : 0.0f) + sqf;
        const float bb0 = (pp_hi ? 0.8f : 0.0f) + sqf;

        const float st2 = (srsi < 0.2f) ? 0.8f : 0.0f;
        const float st0 = (srsi > 0.8f) ? 0.8f : 0.0f;

        const bool  ma_up = ma > 0.1f;
        const bool  ma_dn = ma < -0.1f;
        const float ma2 = ma_up ? 0.7f : 0.0f;
        const float ma0 = ma_dn ? 0.7f : 0.0f;

        const bool st_dn = ssig < -0.1f;
        const bool st_up = ssig > 0.1f;

        // OR of all 3-of-4 conjunctions == majority(>=3 of 4)
        const bool long_sig  = ((int)sb_ + (int)ma_up + (int)st_dn + (int)pp_lo) >= 3;
        const bool short_sig = ((int)sB_ + (int)ma_dn + (int)st_up + (int)pp_hi) >= 3;

        const float hms2 = long_sig  ? 0.9f : 0.0f;
        const float hms0 = short_sig ? 0.9f : 0.0f;

        const float col0 = ha0 + ma0 + st0 + bb0 + 2.0f * hms0;
        const float col2 = ha2 + ma2 + st2 + bb2 + 2.0f * hms2;
        const float col1 = 1.5f;

        const float m  = fmaxf(fmaxf(col0, col2), col1);
        const float e0 = __expf(col0 - m);
        const float e1 = __expf(col1 - m);
        const float e2 = __expf(col2 - m);
        const float inv = 1.0f / (e0 + e1 + e2);

        s_out[tid * 3 + 0] = e0 * inv;
        s_out[tid * 3 + 1] = e1 * inv;
        s_out[tid * 3 + 2] = e2 * inv;
    }
    __syncwarp();                             // order s_out writes within the warp

    // ---- warp-local coalesced store: 96 contiguous floats per warp ----
    // out floats [bid*384 + w*96, +96): 3 coalesced STG.32 per lane.
    const int ob = bid * (RPB * 3) + w * 96;
    #pragma unroll
    for (int j = 0; j < 3; j++)
        out[ob + l + j * 32] = s_out[w * 96 + l + j * 32];
}

extern "C" void kernel_launch(void* const* d_in, const int* in_sizes, int n_in,
                              void* d_out, int out_size) {
    const float4* in4 = (const float4*)d_in[0];
    float* out = (float*)d_out;
    const int n = in_sizes[0] / NCOLS;       // 2,000,000 rows (divisible by 128)
    const int grid = n / RPB;                // 15625 blocks, all full
    indicator_kernel<<<grid, T>>>(in4, out);
}